// round 11
// baseline (speedup 1.0000x reference)
#include <cuda_runtime.h>
#include <cuda_bf16.h>
#include <math.h>
#include <stdint.h>

#define BN 4096          // samples
#define DK 1024          // feature dim
#define TM 128           // CTA tile M = N
#define KC 64            // K elems per chunk
#define NCHUNK (DK / KC) // 16
#define ROWB 144         // padded smem row stride bytes (128 data + 16 pad)
#define ATILE (TM * ROWB)            // 18432 B per operand tile
#define BUFB  (2 * ATILE)            // one stage = A + B = 36864 B
#define NSTAGE 2
#define SMEMB (NSTAGE * BUFB)        // 73728 B
#define INFV 3.4e38f

// ---------------- device scratch (no allocations allowed) ------------------
__device__ __nv_bfloat16 g_Xb[(size_t)BN * DK];         // bf16 copy of X
__device__ float g_norm[BN];                            // ||x_i||^2 (fp32)
__device__ unsigned long long g_rowmin[BN];             // packed (d2_bits<<32 | j)
__device__ unsigned int g_rowmax[BN];                   // d2_bits max over j<i

__device__ __forceinline__ uint32_t smem_to_u32(const void* p) {
    uint32_t a;
    asm("{ .reg .u64 t; cvta.to.shared.u64 t, %1; cvt.u32.u64 %0, t; }" : "=r"(a) : "l"(p));
    return a;
}

// ---------------------------------------------------------------------------
// prep: bf16 convert + row norms + stat init; one warp per row, MLP=8
// ---------------------------------------------------------------------------
__global__ __launch_bounds__(256) void prep_kernel(const float* __restrict__ X) {
    const int w = (blockIdx.x * blockDim.x + threadIdx.x) >> 5;   // row
    const int lane = threadIdx.x & 31;
    const float4* src = (const float4*)(X + (size_t)w * DK);
    uint2* dst = (uint2*)(g_Xb + (size_t)w * DK);

    float4 v[8];
#pragma unroll
    for (int k = 0; k < 8; ++k) v[k] = src[lane + 32 * k];

    float s = 0.0f;
#pragma unroll
    for (int k = 0; k < 8; ++k) {
        __nv_bfloat162 lo = __floats2bfloat162_rn(v[k].x, v[k].y);
        __nv_bfloat162 hi = __floats2bfloat162_rn(v[k].z, v[k].w);
        uint2 o; o.x = *(unsigned*)&lo; o.y = *(unsigned*)&hi;
        dst[lane + 32 * k] = o;
        s = fmaf(v[k].x, v[k].x, fmaf(v[k].y, v[k].y,
            fmaf(v[k].z, v[k].z, fmaf(v[k].w, v[k].w, s))));
    }
#pragma unroll
    for (int off = 16; off > 0; off >>= 1) s += __shfl_xor_sync(0xffffffffu, s, off);
    if (lane == 0) {
        g_norm[w] = s;
        g_rowmin[w] = ~0ull;
        g_rowmax[w] = 0u;
    }
}

// ---------------------------------------------------------------------------
// bf16 mma.sync Gram GEMM: 4 warps (2x2), warp tile 64x64, KC=64, 2-stage
// cp.async, fused row stats (NO G store — fallback recomputes from g_Xb).
// ---------------------------------------------------------------------------
__global__ __launch_bounds__(128) void gram_mma() {
    extern __shared__ __align__(128) char smem[];   // SMEMB

    const int tid = threadIdx.x;
    const int lane = tid & 31;
    const int wid = tid >> 5;
    const uint32_t sbase = smem_to_u32(smem);

    // triangular block map
    int t = blockIdx.x;
    int bi = (int)((sqrtf(8.0f * (float)t + 1.0f) - 1.0f) * 0.5f);
    while ((bi + 1) * (bi + 2) / 2 <= t) ++bi;
    while (bi * (bi + 1) / 2 > t) --bi;
    const int bj = t - bi * (bi + 1) / 2;
    const int i0 = bi * TM, j0 = bj * TM;

    const int mbase = (wid & 1) * 64;
    const int nbase = (wid >> 1) * 64;

    float acc[4][8][4];
#pragma unroll
    for (int a = 0; a < 4; ++a)
#pragma unroll
        for (int b = 0; b < 8; ++b)
#pragma unroll
            for (int c = 0; c < 4; ++c) acc[a][b][c] = 0.0f;

    // loader: lane groups of 8 load one row's 128B contiguously
    const int lseg = tid & 7;            // 16B segment 0..7
    const int lrow0 = tid >> 3;          // rows lrow0 + 16*k, k=0..7

    auto load_chunk = [&](int c, int buf) {
#pragma unroll
        for (int k = 0; k < 8; ++k) {
            int row = lrow0 + k * 16;
            uint32_t dA = sbase + buf * BUFB + row * ROWB + lseg * 16;
            const char* sA = (const char*)(g_Xb + (size_t)(i0 + row) * DK + c * KC) + lseg * 16;
            const char* sB = (const char*)(g_Xb + (size_t)(j0 + row) * DK + c * KC) + lseg * 16;
            asm volatile("cp.async.ca.shared.global [%0], [%1], 16;" :: "r"(dA), "l"(sA));
            asm volatile("cp.async.ca.shared.global [%0], [%1], 16;" :: "r"(dA + ATILE), "l"(sB));
        }
        asm volatile("cp.async.commit_group;" ::: "memory");
    };

    // ldmatrix lane address components (bytes within tile)
    const uint32_t aoffs = (uint32_t)((mbase + (lane & 15)) * ROWB + (lane >> 4) * 16);
    const int brow = ((lane >> 4) << 3) + (lane & 7);
    const uint32_t boffs = (uint32_t)((nbase + brow) * ROWB + ((lane >> 3) & 1) * 16);

    load_chunk(0, 0);

    for (int c = 0; c < NCHUNK; ++c) {
        asm volatile("cp.async.wait_group 0;" ::: "memory");
        __syncthreads();
        if (c + 1 < NCHUNK) load_chunk(c + 1, (c + 1) & 1);

        const uint32_t tA = sbase + (c & 1) * BUFB;
        const uint32_t tB = tA + ATILE;

#pragma unroll
        for (int ks = 0; ks < 4; ++ks) {
            const uint32_t kb = ks * 32;
            uint32_t af[4][4];
#pragma unroll
            for (int mf = 0; mf < 4; ++mf)
                asm volatile("ldmatrix.sync.aligned.m8n8.x4.shared.b16 {%0,%1,%2,%3}, [%4];"
                             : "=r"(af[mf][0]), "=r"(af[mf][1]),
                               "=r"(af[mf][2]), "=r"(af[mf][3])
                             : "r"(tA + aoffs + mf * 16 * ROWB + kb));
#pragma unroll
            for (int np = 0; np < 4; ++np) {
                uint32_t bf[4];
                asm volatile("ldmatrix.sync.aligned.m8n8.x4.shared.b16 {%0,%1,%2,%3}, [%4];"
                             : "=r"(bf[0]), "=r"(bf[1]), "=r"(bf[2]), "=r"(bf[3])
                             : "r"(tB + boffs + np * 16 * ROWB + kb));
#pragma unroll
                for (int mf = 0; mf < 4; ++mf)
#pragma unroll
                    for (int h = 0; h < 2; ++h) {
                        float* cc = acc[mf][2 * np + h];
                        asm volatile(
                            "mma.sync.aligned.m16n8k16.row.col.f32.bf16.bf16.f32 "
                            "{%0,%1,%2,%3}, {%4,%5,%6,%7}, {%8,%9}, {%0,%1,%2,%3};"
                            : "+f"(cc[0]), "+f"(cc[1]), "+f"(cc[2]), "+f"(cc[3])
                            : "r"(af[mf][0]), "r"(af[mf][1]),
                              "r"(af[mf][2]), "r"(af[mf][3]),
                              "r"(bf[2 * h]), "r"(bf[2 * h + 1]));
                    }
            }
        }
    }

    // ---------------- epilogue: row stats from fragments (no G store) -------
#pragma unroll
    for (int mf = 0; mf < 4; ++mf) {
        const int r_lo = i0 + mbase + mf * 16 + (lane >> 2);
        const int r_hi = r_lo + 8;
        const float ni_lo = __ldg(g_norm + r_lo);
        const float ni_hi = __ldg(g_norm + r_hi);
        unsigned long long kmin_lo = ~0ull, kmin_hi = ~0ull;
        float vmax_lo = 0.0f, vmax_hi = 0.0f;

#pragma unroll
        for (int nf = 0; nf < 8; ++nf) {
            const int gj = j0 + nbase + nf * 8 + 2 * (lane & 3);
            const float nj0 = __ldg(g_norm + gj);
            const float nj1 = __ldg(g_norm + gj + 1);
            const float* cf0 = acc[mf][nf];

#pragma unroll
            for (int e = 0; e < 2; ++e) {
                const int gje = gj + e;
                const float nje = e ? nj1 : nj0;
                if (gje < r_lo) {
                    float d2 = fmaxf(fmaf(-2.0f, cf0[e], ni_lo + nje), 0.0f);
                    unsigned long long key =
                        ((unsigned long long)__float_as_uint(d2) << 32) | (unsigned)gje;
                    if (key < kmin_lo) kmin_lo = key;
                    vmax_lo = fmaxf(vmax_lo, d2);
                }
                if (gje < r_hi) {
                    float d2 = fmaxf(fmaf(-2.0f, cf0[2 + e], ni_hi + nje), 0.0f);
                    unsigned long long key =
                        ((unsigned long long)__float_as_uint(d2) << 32) | (unsigned)gje;
                    if (key < kmin_hi) kmin_hi = key;
                    vmax_hi = fmaxf(vmax_hi, d2);
                }
            }
        }
#pragma unroll
        for (int off = 1; off <= 2; off <<= 1) {
            unsigned long long o;
            float m;
            o = __shfl_xor_sync(0xffffffffu, kmin_lo, off); if (o < kmin_lo) kmin_lo = o;
            m = __shfl_xor_sync(0xffffffffu, vmax_lo, off); vmax_lo = fmaxf(vmax_lo, m);
            o = __shfl_xor_sync(0xffffffffu, kmin_hi, off); if (o < kmin_hi) kmin_hi = o;
            m = __shfl_xor_sync(0xffffffffu, vmax_hi, off); vmax_hi = fmaxf(vmax_hi, m);
        }
        if ((lane & 3) == 0) {
            if (kmin_lo != ~0ull) {
                atomicMin(g_rowmin + r_lo, kmin_lo);
                atomicMax(g_rowmax + r_lo, __float_as_uint(vmax_lo));
            }
            if (kmin_hi != ~0ull) {
                atomicMin(g_rowmin + r_hi, kmin_hi);
                atomicMax(g_rowmax + r_hi, __float_as_uint(vmax_hi));
            }
        }
    }
}

// ---------------------------------------------------------------------------
// Speculative scan: parallel prefix + violation check. Exact fallback from
// the first non-insert recomputes distances from g_Xb (slow, never taken on
// this distribution, but preserves correctness).
// ---------------------------------------------------------------------------
__global__ __launch_bounds__(1024, 1) void scan_kernel(const int* __restrict__ labels,
                                                       float* __restrict__ out) {
    extern __shared__ char dyn[];
    float* s_minA = (float*)dyn;                              // 16KB (reused as s_d2)
    float* s_maxA = (float*)(dyn + 16384);                    // 16KB (reused as s_xi)
    float* s_norm = (float*)(dyn + 32768);                    // 16KB (fallback)
    unsigned short* s_ridx = (unsigned short*)(dyn + 49152);  // 8KB  (fallback)
    unsigned char*  s_lab  = (unsigned char*)(dyn + 57344);   // 4KB  (fallback)
    float* s_d2 = s_minA;                                     // alias (fallback)
    float* s_xi = s_maxA;                                     // alias (fallback, 4KB)

    __shared__ float wmin[32], wmax[32];
    __shared__ int s_k;
    __shared__ float r_min[32]; __shared__ int r_arg[32]; __shared__ float r_max[32];
    __shared__ float sh_minD, sh_maxD, sh_R; __shared__ int sh_n;

    const int tid = threadIdx.x;
    const int lane = tid & 31, wid = tid >> 5;

    for (int i = tid; i < BN; i += 1024) {
        if (i == 0) { s_minA[0] = INFV; s_maxA[0] = 0.0f; }
        else {
            unsigned long long p = g_rowmin[i];
            s_minA[i] = sqrtf(__uint_as_float((unsigned)(p >> 32)));
            s_maxA[i] = sqrtf(__uint_as_float(g_rowmax[i]));
        }
    }
    if (tid == 0) s_k = BN;
    __syncthreads();

    const int base = tid * 4;
    float e0 = s_minA[base], e1 = s_minA[base+1], e2 = s_minA[base+2], e3 = s_minA[base+3];
    float f0 = s_maxA[base], f1 = s_maxA[base+1], f2 = s_maxA[base+2], f3 = s_maxA[base+3];
    float im = fminf(fminf(e0, e1), fminf(e2, e3));
    float ix = fmaxf(fmaxf(f0, f1), fmaxf(f2, f3));

#pragma unroll
    for (int off = 1; off < 32; off <<= 1) {
        float o  = __shfl_up_sync(0xffffffffu, im, off); if (lane >= off) im = fminf(im, o);
        float o2 = __shfl_up_sync(0xffffffffu, ix, off); if (lane >= off) ix = fmaxf(ix, o2);
    }
    if (lane == 31) { wmin[wid] = im; wmax[wid] = ix; }
    __syncthreads();
    if (wid == 0) {
        float a = wmin[lane], b = wmax[lane];
#pragma unroll
        for (int off = 1; off < 32; off <<= 1) {
            float o  = __shfl_up_sync(0xffffffffu, a, off); if (lane >= off) a = fminf(a, o);
            float o2 = __shfl_up_sync(0xffffffffu, b, off); if (lane >= off) b = fmaxf(b, o2);
        }
        wmin[lane] = a; wmax[lane] = b;
    }
    __syncthreads();

    float excl_min = INFV, excl_max = 0.0f;
    if (wid > 0) { excl_min = wmin[wid - 1]; excl_max = wmax[wid - 1]; }
    float pm = __shfl_up_sync(0xffffffffu, im, 1);
    float px = __shfl_up_sync(0xffffffffu, ix, 1);
    if (lane > 0) { excl_min = fminf(excl_min, pm); excl_max = fmaxf(excl_max, px); }

    {
        float run_min = excl_min, run_max = excl_max;
        float e[4] = {e0, e1, e2, e3};
        float f[4] = {f0, f1, f2, f3};
        int myviol = BN;
#pragma unroll
        for (int tI = 0; tI < 4; ++tI) {
            int i = base + tI;
            if (i >= 1) {
                float Rin = (i <= 1) ? 1.0f : (run_min + run_max) / 3.0f;
                if (!(e[tI] > Rin) && myviol == BN) myviol = i;
            }
            run_min = fminf(run_min, e[tI]);
            run_max = fmaxf(run_max, f[tI]);
        }
        if (myviol < BN) atomicMin(&s_k, myviol);
    }
    __syncthreads();
    const int k = s_k;

    for (int i = tid; i < k; i += 1024) out[i] = (float)labels[i];
    if (k == BN) return;

    // ================= exact fallback from first non-insert =================
    if (tid == 0) {
        unsigned arg = (unsigned)(g_rowmin[k] & 0xffffffffu);
        out[k] = (float)labels[arg];
        float a = INFV, b = 0.0f;
        for (int i = 1; i <= k; ++i) { a = fminf(a, s_minA[i]); b = fmaxf(b, s_maxA[i]); }
        sh_minD = a; sh_maxD = b; sh_R = (a + b) / 3.0f; sh_n = k;
    }
    for (int i = tid; i < BN; i += 1024) {
        s_norm[i] = g_norm[i];
        s_lab[i]  = (unsigned char)labels[i];
    }
    for (int j = tid; j < k; j += 1024) s_ridx[j] = (unsigned short)j;
    __syncthreads();

    for (int i = k + 1; i < BN; ++i) {
        const int n = sh_n;
        const float ni = s_norm[i];

        // stage x_i (fp32) into smem
        for (int c = tid; c < DK; c += 1024)
            s_xi[c] = __bfloat162float(g_Xb[(size_t)i * DK + c]);
        __syncthreads();

        // warp w computes d2 for refs j = w, w+32, ... ; lanes split DK
        for (int j = wid; j < n; j += 32) {
            const int r = s_ridx[j];
            const __nv_bfloat16* xr = g_Xb + (size_t)r * DK;
            float dot = 0.0f;
            for (int c = lane; c < DK; c += 32)
                dot = fmaf(s_xi[c], __bfloat162float(xr[c]), dot);
#pragma unroll
            for (int off = 16; off > 0; off >>= 1)
                dot += __shfl_xor_sync(0xffffffffu, dot, off);
            if (lane == 0)
                s_d2[j] = fmaf(-2.0f, dot, ni + s_norm[r]);
        }
        __syncthreads();

        float lmin = INFV;
        int   larg = 0x7fffffff;
        float lmax = -INFV;
        for (int j = tid; j < n; j += 1024) {
            float d2 = s_d2[j];
            if (d2 < lmin) { lmin = d2; larg = j; }
            lmax = fmaxf(lmax, d2);
        }
#pragma unroll
        for (int off = 16; off > 0; off >>= 1) {
            float v = __shfl_down_sync(0xffffffffu, lmin, off);
            int   a = __shfl_down_sync(0xffffffffu, larg, off);
            float m = __shfl_down_sync(0xffffffffu, lmax, off);
            if (v < lmin || (v == lmin && a < larg)) { lmin = v; larg = a; }
            lmax = fmaxf(lmax, m);
        }
        if (lane == 0) { r_min[wid] = lmin; r_arg[wid] = larg; r_max[wid] = lmax; }
        __syncthreads();

        if (tid == 0) {
            float bm = r_min[0]; int ba = r_arg[0]; float bx = r_max[0];
#pragma unroll
            for (int w = 1; w < 32; ++w) {
                float v = r_min[w]; int a = r_arg[w];
                if (v < bm || (v == bm && a < ba)) { bm = v; ba = a; }
                bx = fmaxf(bx, r_max[w]);
            }
            const float min_act = sqrtf(fmaxf(bm, 0.0f));
            const bool insert = (min_act > sh_R);
            float pred;
            if (insert) {
                s_ridx[n] = (unsigned short)i;
                sh_n = n + 1;
                pred = (float)s_lab[i];
            } else {
                pred = (float)s_lab[s_ridx[ba]];
            }
            const float max_act = sqrtf(fmaxf(bx, 0.0f));
            sh_minD = fminf(sh_minD, min_act);
            sh_maxD = fmaxf(sh_maxD, max_act);
            sh_R = (sh_minD + sh_maxD) / 3.0f;
            out[i] = pred;
        }
        __syncthreads();
    }
}

// ---------------------------------------------------------------------------
extern "C" void kernel_launch(void* const* d_in, const int* in_sizes, int n_in,
                              void* d_out, int out_size) {
    const float* x      = (const float*)d_in[0];
    const int*   labels = (const int*)d_in[1];
    float*       out    = (float*)d_out;

    static bool attr_set = false;
    if (!attr_set) {
        cudaFuncSetAttribute(scan_kernel, cudaFuncAttributeMaxDynamicSharedMemorySize, 61440);
        cudaFuncSetAttribute(gram_mma, cudaFuncAttributeMaxDynamicSharedMemorySize, SMEMB);
        attr_set = true;
    }

    prep_kernel<<<BN / 8, 256>>>(x);
    const int nb = BN / TM;
    gram_mma<<<nb * (nb + 1) / 2, 128, SMEMB>>>();
    scan_kernel<<<1, 1024, 61440>>>(labels, out);
}

// round 12
// speedup vs baseline: 1.1240x; 1.1240x over previous
#include <cuda_runtime.h>
#include <cuda_bf16.h>
#include <cuda_fp16.h>
#include <cuda_fp8.h>
#include <math.h>
#include <stdint.h>

#define BN 4096          // samples
#define DK 1024          // feature dim
#define TM 128           // CTA tile M = N
#define KC 128           // K elems per chunk (fp8: 128 B per row per chunk)
#define NCHUNK (DK / KC) // 8
#define ROWB 144         // padded smem row stride bytes (128 data + 16 pad)
#define ATILE (TM * ROWB)            // 18432 B per operand tile
#define BUFB  (2 * ATILE)            // one stage = A + B = 36864 B
#define NSTAGE 2
#define SMEMB (NSTAGE * BUFB)        // 73728 B
#define INFV 3.4e38f

// ---------------- device scratch (no allocations allowed) ------------------
__device__ unsigned char g_Xq[(size_t)BN * DK];         // e4m3 copy of X
__device__ float g_norm[BN];                            // ||x_i||^2 (fp32)
__device__ unsigned long long g_rowmin[BN];             // packed (d2_bits<<32 | j)
__device__ unsigned int g_rowmax[BN];                   // d2_bits max over j<i

__device__ __forceinline__ uint32_t smem_to_u32(const void* p) {
    uint32_t a;
    asm("{ .reg .u64 t; cvta.to.shared.u64 t, %1; cvt.u32.u64 %0, t; }" : "=r"(a) : "l"(p));
    return a;
}

__device__ __forceinline__ uint32_t cvt4_e4m3(float4 v) {
    __nv_fp8x2_storage_t lo =
        __nv_cvt_float2_to_fp8x2(make_float2(v.x, v.y), __NV_SATFINITE, __NV_E4M3);
    __nv_fp8x2_storage_t hi =
        __nv_cvt_float2_to_fp8x2(make_float2(v.z, v.w), __NV_SATFINITE, __NV_E4M3);
    return (uint32_t)lo | ((uint32_t)hi << 16);
}

__device__ __forceinline__ float fp8_to_f(unsigned char b) {
    __half_raw h = __nv_cvt_fp8_to_halfraw((__nv_fp8_storage_t)b, __NV_E4M3);
    __half hh; *(__half_raw*)&hh = h;
    return __half2float(hh);
}

// ---------------------------------------------------------------------------
// prep: e4m3 convert + fp32 row norms + stat init; one warp per row, MLP=8
// ---------------------------------------------------------------------------
__global__ __launch_bounds__(256) void prep_kernel(const float* __restrict__ X) {
    const int w = (blockIdx.x * blockDim.x + threadIdx.x) >> 5;   // row
    const int lane = threadIdx.x & 31;
    const float4* src = (const float4*)(X + (size_t)w * DK);
    uint32_t* dst = (uint32_t*)(g_Xq + (size_t)w * DK);

    float4 v[8];
#pragma unroll
    for (int k = 0; k < 8; ++k) v[k] = src[lane + 32 * k];

    float s = 0.0f;
#pragma unroll
    for (int k = 0; k < 8; ++k) {
        dst[lane + 32 * k] = cvt4_e4m3(v[k]);
        s = fmaf(v[k].x, v[k].x, fmaf(v[k].y, v[k].y,
            fmaf(v[k].z, v[k].z, fmaf(v[k].w, v[k].w, s))));
    }
#pragma unroll
    for (int off = 16; off > 0; off >>= 1) s += __shfl_xor_sync(0xffffffffu, s, off);
    if (lane == 0) {
        g_norm[w] = s;
        g_rowmin[w] = ~0ull;
        g_rowmax[w] = 0u;
    }
}

// ---------------------------------------------------------------------------
// e4m3 mma.sync Gram GEMM: 4 warps (2x2), warp tile 64x64, m16n8k32, KC=128,
// 2-stage cp.async, fused row stats (fallback recomputes from g_Xq).
// ---------------------------------------------------------------------------
__global__ __launch_bounds__(128) void gram_mma() {
    extern __shared__ __align__(128) char smem[];   // SMEMB

    const int tid = threadIdx.x;
    const int lane = tid & 31;
    const int wid = tid >> 5;
    const uint32_t sbase = smem_to_u32(smem);

    // triangular block map
    int t = blockIdx.x;
    int bi = (int)((sqrtf(8.0f * (float)t + 1.0f) - 1.0f) * 0.5f);
    while ((bi + 1) * (bi + 2) / 2 <= t) ++bi;
    while (bi * (bi + 1) / 2 > t) --bi;
    const int bj = t - bi * (bi + 1) / 2;
    const int i0 = bi * TM, j0 = bj * TM;

    const int mbase = (wid & 1) * 64;
    const int nbase = (wid >> 1) * 64;

    float acc[4][8][4];
#pragma unroll
    for (int a = 0; a < 4; ++a)
#pragma unroll
        for (int b = 0; b < 8; ++b)
#pragma unroll
            for (int c = 0; c < 4; ++c) acc[a][b][c] = 0.0f;

    // loader: lane groups of 8 load one row's 128B contiguously
    const int lseg = tid & 7;            // 16B segment 0..7
    const int lrow0 = tid >> 3;          // rows lrow0 + 16*k, k=0..7

    auto load_chunk = [&](int c, int buf) {
#pragma unroll
        for (int k = 0; k < 8; ++k) {
            int row = lrow0 + k * 16;
            uint32_t dA = sbase + buf * BUFB + row * ROWB + lseg * 16;
            const char* sA = (const char*)(g_Xq + (size_t)(i0 + row) * DK + c * KC) + lseg * 16;
            const char* sB = (const char*)(g_Xq + (size_t)(j0 + row) * DK + c * KC) + lseg * 16;
            asm volatile("cp.async.ca.shared.global [%0], [%1], 16;" :: "r"(dA), "l"(sA));
            asm volatile("cp.async.ca.shared.global [%0], [%1], 16;" :: "r"(dA + ATILE), "l"(sB));
        }
        asm volatile("cp.async.commit_group;" ::: "memory");
    };

    // ldmatrix lane address components (bytes within tile)
    const uint32_t aoffs = (uint32_t)((mbase + (lane & 15)) * ROWB + (lane >> 4) * 16);
    const int brow = ((lane >> 4) << 3) + (lane & 7);
    const uint32_t boffs = (uint32_t)((nbase + brow) * ROWB + ((lane >> 3) & 1) * 16);

    load_chunk(0, 0);

    for (int c = 0; c < NCHUNK; ++c) {
        asm volatile("cp.async.wait_group 0;" ::: "memory");
        __syncthreads();
        if (c + 1 < NCHUNK) load_chunk(c + 1, (c + 1) & 1);

        const uint32_t tA = sbase + (c & 1) * BUFB;
        const uint32_t tB = tA + ATILE;

#pragma unroll
        for (int ks = 0; ks < 4; ++ks) {
            const uint32_t kb = ks * 32;       // 32 fp8 = 32 bytes per k-step
            uint32_t af[4][4];
#pragma unroll
            for (int mf = 0; mf < 4; ++mf)
                asm volatile("ldmatrix.sync.aligned.m8n8.x4.shared.b16 {%0,%1,%2,%3}, [%4];"
                             : "=r"(af[mf][0]), "=r"(af[mf][1]),
                               "=r"(af[mf][2]), "=r"(af[mf][3])
                             : "r"(tA + aoffs + mf * 16 * ROWB + kb));
#pragma unroll
            for (int np = 0; np < 4; ++np) {
                uint32_t bf[4];
                asm volatile("ldmatrix.sync.aligned.m8n8.x4.shared.b16 {%0,%1,%2,%3}, [%4];"
                             : "=r"(bf[0]), "=r"(bf[1]), "=r"(bf[2]), "=r"(bf[3])
                             : "r"(tB + boffs + np * 16 * ROWB + kb));
#pragma unroll
                for (int mf = 0; mf < 4; ++mf)
#pragma unroll
                    for (int h = 0; h < 2; ++h) {
                        float* cc = acc[mf][2 * np + h];
                        asm volatile(
                            "mma.sync.aligned.m16n8k32.row.col.f32.e4m3.e4m3.f32 "
                            "{%0,%1,%2,%3}, {%4,%5,%6,%7}, {%8,%9}, {%0,%1,%2,%3};"
                            : "+f"(cc[0]), "+f"(cc[1]), "+f"(cc[2]), "+f"(cc[3])
                            : "r"(af[mf][0]), "r"(af[mf][1]),
                              "r"(af[mf][2]), "r"(af[mf][3]),
                              "r"(bf[2 * h]), "r"(bf[2 * h + 1]));
                    }
            }
        }
    }

    // ---------------- epilogue: row stats from fragments --------------------
#pragma unroll
    for (int mf = 0; mf < 4; ++mf) {
        const int r_lo = i0 + mbase + mf * 16 + (lane >> 2);
        const int r_hi = r_lo + 8;
        const float ni_lo = __ldg(g_norm + r_lo);
        const float ni_hi = __ldg(g_norm + r_hi);
        unsigned long long kmin_lo = ~0ull, kmin_hi = ~0ull;
        float vmax_lo = 0.0f, vmax_hi = 0.0f;

#pragma unroll
        for (int nf = 0; nf < 8; ++nf) {
            const int gj = j0 + nbase + nf * 8 + 2 * (lane & 3);
            const float nj0 = __ldg(g_norm + gj);
            const float nj1 = __ldg(g_norm + gj + 1);
            const float* cf0 = acc[mf][nf];

#pragma unroll
            for (int e = 0; e < 2; ++e) {
                const int gje = gj + e;
                const float nje = e ? nj1 : nj0;
                if (gje < r_lo) {
                    float d2 = fmaxf(fmaf(-2.0f, cf0[e], ni_lo + nje), 0.0f);
                    unsigned long long key =
                        ((unsigned long long)__float_as_uint(d2) << 32) | (unsigned)gje;
                    if (key < kmin_lo) kmin_lo = key;
                    vmax_lo = fmaxf(vmax_lo, d2);
                }
                if (gje < r_hi) {
                    float d2 = fmaxf(fmaf(-2.0f, cf0[2 + e], ni_hi + nje), 0.0f);
                    unsigned long long key =
                        ((unsigned long long)__float_as_uint(d2) << 32) | (unsigned)gje;
                    if (key < kmin_hi) kmin_hi = key;
                    vmax_hi = fmaxf(vmax_hi, d2);
                }
            }
        }
#pragma unroll
        for (int off = 1; off <= 2; off <<= 1) {
            unsigned long long o;
            float m;
            o = __shfl_xor_sync(0xffffffffu, kmin_lo, off); if (o < kmin_lo) kmin_lo = o;
            m = __shfl_xor_sync(0xffffffffu, vmax_lo, off); vmax_lo = fmaxf(vmax_lo, m);
            o = __shfl_xor_sync(0xffffffffu, kmin_hi, off); if (o < kmin_hi) kmin_hi = o;
            m = __shfl_xor_sync(0xffffffffu, vmax_hi, off); vmax_hi = fmaxf(vmax_hi, m);
        }
        if ((lane & 3) == 0) {
            if (kmin_lo != ~0ull) {
                atomicMin(g_rowmin + r_lo, kmin_lo);
                atomicMax(g_rowmax + r_lo, __float_as_uint(vmax_lo));
            }
            if (kmin_hi != ~0ull) {
                atomicMin(g_rowmin + r_hi, kmin_hi);
                atomicMax(g_rowmax + r_hi, __float_as_uint(vmax_hi));
            }
        }
    }
}

// ---------------------------------------------------------------------------
// Speculative scan: parallel prefix + violation check. Exact fallback from
// the first non-insert recomputes distances from g_Xq (never taken on this
// distribution, preserves correctness).
// ---------------------------------------------------------------------------
__global__ __launch_bounds__(1024, 1) void scan_kernel(const int* __restrict__ labels,
                                                       float* __restrict__ out) {
    extern __shared__ char dyn[];
    float* s_minA = (float*)dyn;                              // 16KB (reused as s_d2)
    float* s_maxA = (float*)(dyn + 16384);                    // 16KB (reused as s_xi)
    float* s_norm = (float*)(dyn + 32768);                    // 16KB (fallback)
    unsigned short* s_ridx = (unsigned short*)(dyn + 49152);  // 8KB  (fallback)
    unsigned char*  s_lab  = (unsigned char*)(dyn + 57344);   // 4KB  (fallback)
    float* s_d2 = s_minA;                                     // alias (fallback)
    float* s_xi = s_maxA;                                     // alias (fallback, 4KB)

    __shared__ float wmin[32], wmax[32];
    __shared__ int s_k;
    __shared__ float r_min[32]; __shared__ int r_arg[32]; __shared__ float r_max[32];
    __shared__ float sh_minD, sh_maxD, sh_R; __shared__ int sh_n;

    const int tid = threadIdx.x;
    const int lane = tid & 31, wid = tid >> 5;

    for (int i = tid; i < BN; i += 1024) {
        if (i == 0) { s_minA[0] = INFV; s_maxA[0] = 0.0f; }
        else {
            unsigned long long p = g_rowmin[i];
            s_minA[i] = sqrtf(__uint_as_float((unsigned)(p >> 32)));
            s_maxA[i] = sqrtf(__uint_as_float(g_rowmax[i]));
        }
    }
    if (tid == 0) s_k = BN;
    __syncthreads();

    const int base = tid * 4;
    float e0 = s_minA[base], e1 = s_minA[base+1], e2 = s_minA[base+2], e3 = s_minA[base+3];
    float f0 = s_maxA[base], f1 = s_maxA[base+1], f2 = s_maxA[base+2], f3 = s_maxA[base+3];
    float im = fminf(fminf(e0, e1), fminf(e2, e3));
    float ix = fmaxf(fmaxf(f0, f1), fmaxf(f2, f3));

#pragma unroll
    for (int off = 1; off < 32; off <<= 1) {
        float o  = __shfl_up_sync(0xffffffffu, im, off); if (lane >= off) im = fminf(im, o);
        float o2 = __shfl_up_sync(0xffffffffu, ix, off); if (lane >= off) ix = fmaxf(ix, o2);
    }
    if (lane == 31) { wmin[wid] = im; wmax[wid] = ix; }
    __syncthreads();
    if (wid == 0) {
        float a = wmin[lane], b = wmax[lane];
#pragma unroll
        for (int off = 1; off < 32; off <<= 1) {
            float o  = __shfl_up_sync(0xffffffffu, a, off); if (lane >= off) a = fminf(a, o);
            float o2 = __shfl_up_sync(0xffffffffu, b, off); if (lane >= off) b = fmaxf(b, o2);
        }
        wmin[lane] = a; wmax[lane] = b;
    }
    __syncthreads();

    float excl_min = INFV, excl_max = 0.0f;
    if (wid > 0) { excl_min = wmin[wid - 1]; excl_max = wmax[wid - 1]; }
    float pm = __shfl_up_sync(0xffffffffu, im, 1);
    float px = __shfl_up_sync(0xffffffffu, ix, 1);
    if (lane > 0) { excl_min = fminf(excl_min, pm); excl_max = fmaxf(excl_max, px); }

    {
        float run_min = excl_min, run_max = excl_max;
        float e[4] = {e0, e1, e2, e3};
        float f[4] = {f0, f1, f2, f3};
        int myviol = BN;
#pragma unroll
        for (int tI = 0; tI < 4; ++tI) {
            int i = base + tI;
            if (i >= 1) {
                float Rin = (i <= 1) ? 1.0f : (run_min + run_max) / 3.0f;
                if (!(e[tI] > Rin) && myviol == BN) myviol = i;
            }
            run_min = fminf(run_min, e[tI]);
            run_max = fmaxf(run_max, f[tI]);
        }
        if (myviol < BN) atomicMin(&s_k, myviol);
    }
    __syncthreads();
    const int k = s_k;

    for (int i = tid; i < k; i += 1024) out[i] = (float)labels[i];
    if (k == BN) return;

    // ================= exact fallback from first non-insert =================
    if (tid == 0) {
        unsigned arg = (unsigned)(g_rowmin[k] & 0xffffffffu);
        out[k] = (float)labels[arg];
        float a = INFV, b = 0.0f;
        for (int i = 1; i <= k; ++i) { a = fminf(a, s_minA[i]); b = fmaxf(b, s_maxA[i]); }
        sh_minD = a; sh_maxD = b; sh_R = (a + b) / 3.0f; sh_n = k;
    }
    for (int i = tid; i < BN; i += 1024) {
        s_norm[i] = g_norm[i];
        s_lab[i]  = (unsigned char)labels[i];
    }
    for (int j = tid; j < k; j += 1024) s_ridx[j] = (unsigned short)j;
    __syncthreads();

    for (int i = k + 1; i < BN; ++i) {
        const int n = sh_n;
        const float ni = s_norm[i];

        // stage x_i (fp32 from fp8) into smem
        for (int c = tid; c < DK; c += 1024)
            s_xi[c] = fp8_to_f(g_Xq[(size_t)i * DK + c]);
        __syncthreads();

        // warp w computes d2 for refs j = w, w+32, ... ; lanes split DK
        for (int j = wid; j < n; j += 32) {
            const int r = s_ridx[j];
            const unsigned char* xr = g_Xq + (size_t)r * DK;
            float dot = 0.0f;
            for (int c = lane; c < DK; c += 32)
                dot = fmaf(s_xi[c], fp8_to_f(xr[c]), dot);
#pragma unroll
            for (int off = 16; off > 0; off >>= 1)
                dot += __shfl_xor_sync(0xffffffffu, dot, off);
            if (lane == 0)
                s_d2[j] = fmaf(-2.0f, dot, ni + s_norm[r]);
        }
        __syncthreads();

        float lmin = INFV;
        int   larg = 0x7fffffff;
        float lmax = -INFV;
        for (int j = tid; j < n; j += 1024) {
            float d2 = s_d2[j];
            if (d2 < lmin) { lmin = d2; larg = j; }
            lmax = fmaxf(lmax, d2);
        }
#pragma unroll
        for (int off = 16; off > 0; off >>= 1) {
            float v = __shfl_down_sync(0xffffffffu, lmin, off);
            int   a = __shfl_down_sync(0xffffffffu, larg, off);
            float m = __shfl_down_sync(0xffffffffu, lmax, off);
            if (v < lmin || (v == lmin && a < larg)) { lmin = v; larg = a; }
            lmax = fmaxf(lmax, m);
        }
        if (lane == 0) { r_min[wid] = lmin; r_arg[wid] = larg; r_max[wid] = lmax; }
        __syncthreads();

        if (tid == 0) {
            float bm = r_min[0]; int ba = r_arg[0]; float bx = r_max[0];
#pragma unroll
            for (int w = 1; w < 32; ++w) {
                float v = r_min[w]; int a = r_arg[w];
                if (v < bm || (v == bm && a < ba)) { bm = v; ba = a; }
                bx = fmaxf(bx, r_max[w]);
            }
            const float min_act = sqrtf(fmaxf(bm, 0.0f));
            const bool insert = (min_act > sh_R);
            float pred;
            if (insert) {
                s_ridx[n] = (unsigned short)i;
                sh_n = n + 1;
                pred = (float)s_lab[i];
            } else {
                pred = (float)s_lab[s_ridx[ba]];
            }
            const float max_act = sqrtf(fmaxf(bx, 0.0f));
            sh_minD = fminf(sh_minD, min_act);
            sh_maxD = fmaxf(sh_maxD, max_act);
            sh_R = (sh_minD + sh_maxD) / 3.0f;
            out[i] = pred;
        }
        __syncthreads();
    }
}

// ---------------------------------------------------------------------------
extern "C" void kernel_launch(void* const* d_in, const int* in_sizes, int n_in,
                              void* d_out, int out_size) {
    const float* x      = (const float*)d_in[0];
    const int*   labels = (const int*)d_in[1];
    float*       out    = (float*)d_out;

    static bool attr_set = false;
    if (!attr_set) {
        cudaFuncSetAttribute(scan_kernel, cudaFuncAttributeMaxDynamicSharedMemorySize, 61440);
        cudaFuncSetAttribute(gram_mma, cudaFuncAttributeMaxDynamicSharedMemorySize, SMEMB);
        attr_set = true;
    }

    prep_kernel<<<BN / 8, 256>>>(x);
    const int nb = BN / TM;
    gram_mma<<<nb * (nb + 1) / 2, 128, SMEMB>>>();
    scan_kernel<<<1, 1024, 61440>>>(labels, out);
}